// round 2
// baseline (speedup 1.0000x reference)
#include <cuda_runtime.h>
#include <cstdint>

#define N_NODES 100000
#define N_EDGES 1600000
#define N_PRED  500000
#define D       64

// ---------------- device scratch (alloc-free rule: static globals) ----------
__device__ int   g_deg_out[N_NODES];
__device__ int   g_deg_in [N_NODES];
__device__ float g_norm_out[N_NODES];
__device__ float g_norm_in [N_NODES];
__device__ __align__(16) float g_xn [(size_t)N_NODES * D]; // scaled messages
__device__ __align__(16) float g_agg[(size_t)N_NODES * D]; // scatter target
__device__ __align__(16) float g_h  [(size_t)N_NODES * D]; // layer-2 output
__device__ __align__(16) float g_p  [(size_t)N_NODES * 16];// [pA | pB] per node

// ---------------- kernels ---------------------------------------------------

__global__ void k_zero_deg() {
    int i = blockIdx.x * blockDim.x + threadIdx.x;
    if (i < N_NODES) { g_deg_out[i] = 0; g_deg_in[i] = 0; }
}

__global__ void k_degree(const int* __restrict__ src, const int* __restrict__ dst) {
    int e = blockIdx.x * blockDim.x + threadIdx.x;
    if (e < N_EDGES) {
        atomicAdd(&g_deg_out[__ldg(&src[e])], 1);
        atomicAdd(&g_deg_in [__ldg(&dst[e])], 1);
    }
}

__global__ void k_norms() {
    int i = blockIdx.x * blockDim.x + threadIdx.x;
    if (i < N_NODES) {
        int dou = g_deg_out[i];
        int din = g_deg_in[i];
        g_norm_out[i] = dou > 0 ? rsqrtf((float)dou) : 0.f;
        g_norm_in [i] = din > 0 ? rsqrtf((float)din) : 0.f;
    }
}

// g_xn = x * norm_out (rowwise), g_agg = 0.  One float4 per thread.
__global__ void k_scale_init(const float* __restrict__ x) {
    int i = blockIdx.x * blockDim.x + threadIdx.x;        // over N_NODES*16
    if (i < N_NODES * (D / 4)) {
        int node = i >> 4;
        float no = g_norm_out[node];
        float4 v = ((const float4*)x)[i];
        v.x *= no; v.y *= no; v.z *= no; v.w *= no;
        ((float4*)g_xn)[i]  = v;
        ((float4*)g_agg)[i] = make_float4(0.f, 0.f, 0.f, 0.f);
    }
}

// Scatter-add: 16 lanes per edge, float4 per lane, vector red to L2.
__global__ void k_scatter(const int* __restrict__ src, const int* __restrict__ dst) {
    long long gid = (long long)blockIdx.x * blockDim.x + threadIdx.x;
    long long e = gid >> 4;
    if (e >= N_EDGES) return;
    int j = (int)(gid & 15);
    int s = __ldg(&src[e]);
    int d = __ldg(&dst[e]);
    float4 v = ((const float4*)(g_xn + (size_t)s * D))[j];
    float* daddr = g_agg + (size_t)d * D + j * 4;
    asm volatile("red.global.add.v4.f32 [%0], {%1,%2,%3,%4};"
                 :: "l"(daddr), "f"(v.x), "f"(v.y), "f"(v.z), "f"(v.w)
                 : "memory");
}

// Node update: out = f((agg*norm_in) @ W + b).
// MODE 0: relu, then *norm_out, write into g_xn, and zero g_agg (prep layer 2).
// MODE 1: plain, write into g_h.
// W columns live in registers (fully unrolled), node rows staged in smem.
template <int MODE>
__global__ void __launch_bounds__(256, 2)
k_node_update(const float* __restrict__ W, const float* __restrict__ b) {
    const int t = threadIdx.x;
    const int c = t & 63;    // output column
    const int r = t >> 6;    // node slot within pass (0..3)

    float w[D];
#pragma unroll
    for (int kk = 0; kk < D; kk++) w[kk] = __ldg(&W[kk * D + c]);
    const float bc = __ldg(&b[c]);

    __shared__ __align__(16) float vs[4][D];

    for (int base = blockIdx.x * 4; base < N_NODES; base += gridDim.x * 4) {
        int node = base + r;
        bool ok = (node < N_NODES);
        float ni = ok ? g_norm_in[node] : 0.f;
        size_t off = (size_t)(ok ? node : 0) * D + c;
        if (ok) {
            vs[r][c] = g_agg[off] * ni;
            if (MODE == 0) g_agg[off] = 0.f;   // zero for layer-2 scatter
        }
        __syncthreads();

        float acc = bc;
        const float4* vrow = (const float4*)vs[r];
#pragma unroll
        for (int q = 0; q < D / 4; q++) {
            float4 vv = vrow[q];
            acc = fmaf(vv.x, w[4 * q + 0], acc);
            acc = fmaf(vv.y, w[4 * q + 1], acc);
            acc = fmaf(vv.z, w[4 * q + 2], acc);
            acc = fmaf(vv.w, w[4 * q + 3], acc);
        }
        if (ok) {
            if (MODE == 0) {
                acc = fmaxf(acc, 0.f) * g_norm_out[node];
                g_xn[off] = acc;
            } else {
                g_h[off] = acc;
            }
        }
        __syncthreads();
    }
}

// Per-node predictor projection:
// g_p[n][0:8] = h[n] @ Wp[0:64], g_p[n][8:16] = h[n] @ Wp[64:128]
__global__ void __launch_bounds__(256, 2)
k_project(const float* __restrict__ Wp) {
    const int t = threadIdx.x;
    const int c  = t & 15;   // output column within 16
    const int nl = t >> 4;   // node slot (0..15)

    const int rowoff = (c < 8) ? 0 : 64;
    const int cc = c & 7;
    float w[D];
#pragma unroll
    for (int kk = 0; kk < D; kk++) w[kk] = __ldg(&Wp[(rowoff + kk) * 8 + cc]);

    __shared__ __align__(16) float hs[16 * D];

    for (int base = blockIdx.x * 16; base < N_NODES; base += gridDim.x * 16) {
        if (base + (t >> 4) < N_NODES)   // each thread loads 4 floats of one row
            ((float4*)hs)[t] = ((const float4*)(g_h + (size_t)base * D))[t];
        __syncthreads();

        int node = base + nl;
        if (node < N_NODES) {
            float acc = 0.f;
            const float4* vrow = (const float4*)(hs + nl * D);
#pragma unroll
            for (int q = 0; q < D / 4; q++) {
                float4 vv = vrow[q];
                acc = fmaf(vv.x, w[4 * q + 0], acc);
                acc = fmaf(vv.y, w[4 * q + 1], acc);
                acc = fmaf(vv.z, w[4 * q + 2], acc);
                acc = fmaf(vv.w, w[4 * q + 3], acc);
            }
            g_p[(size_t)node * 16 + c] = acc;
        }
        __syncthreads();
    }
}

// Final edge scores: out[e] = pA[psrc[e]] + pB[pdst[e]] + bp
__global__ void k_edge_pred(const int* __restrict__ psrc, const int* __restrict__ pdst,
                            const float* __restrict__ bp, float* __restrict__ out) {
    int e = blockIdx.x * blockDim.x + threadIdx.x;
    if (e >= N_PRED) return;
    int u = __ldg(&psrc[e]);
    int v = __ldg(&pdst[e]);
    const float4* pa = (const float4*)(g_p + (size_t)u * 16);
    const float4* pb = (const float4*)(g_p + (size_t)v * 16 + 8);
    float4 a0 = pa[0], a1 = pa[1];
    float4 c0 = pb[0], c1 = pb[1];
    float4 bp0 = ((const float4*)bp)[0];
    float4 bp1 = ((const float4*)bp)[1];
    float4 o0 = make_float4(a0.x + c0.x + bp0.x, a0.y + c0.y + bp0.y,
                            a0.z + c0.z + bp0.z, a0.w + c0.w + bp0.w);
    float4 o1 = make_float4(a1.x + c1.x + bp1.x, a1.y + c1.y + bp1.y,
                            a1.z + c1.z + bp1.z, a1.w + c1.w + bp1.w);
    ((float4*)out)[(size_t)e * 2 + 0] = o0;
    ((float4*)out)[(size_t)e * 2 + 1] = o1;
}

// ---------------- launch ----------------------------------------------------

extern "C" void kernel_launch(void* const* d_in, const int* in_sizes, int n_in,
                              void* d_out, int out_size) {
    const float* x    = (const float*)d_in[0];
    const int*   src  = (const int*)  d_in[1];
    const int*   dst  = (const int*)  d_in[2];
    const int*   psrc = (const int*)  d_in[3];
    const int*   pdst = (const int*)  d_in[4];
    const float* W1   = (const float*)d_in[5];
    const float* b1   = (const float*)d_in[6];
    const float* W2   = (const float*)d_in[7];
    const float* b2   = (const float*)d_in[8];
    const float* Wp   = (const float*)d_in[9];
    const float* bp   = (const float*)d_in[10];
    float* out = (float*)d_out;

    const int TB = 256;
    // degrees + norms
    k_zero_deg<<<(N_NODES + TB - 1) / TB, TB>>>();
    k_degree  <<<(N_EDGES + TB - 1) / TB, TB>>>(src, dst);
    k_norms   <<<(N_NODES + TB - 1) / TB, TB>>>();

    // layer 1
    k_scale_init<<<(N_NODES * (D / 4) + TB - 1) / TB, TB>>>(x);
    k_scatter<<<(int)(((size_t)N_EDGES * 16 + TB - 1) / TB), TB>>>(src, dst);
    k_node_update<0><<<1024, TB>>>(W1, b1);   // relu + *norm_out -> g_xn, zeros g_agg

    // layer 2
    k_scatter<<<(int)(((size_t)N_EDGES * 16 + TB - 1) / TB), TB>>>(src, dst);
    k_node_update<1><<<1024, TB>>>(W2, b2);   // -> g_h

    // predictor
    k_project<<<(N_NODES + 15) / 16, TB>>>(Wp);
    k_edge_pred<<<(N_PRED + TB - 1) / TB, TB>>>(psrc, pdst, bp, out);
}

// round 4
// speedup vs baseline: 1.4170x; 1.4170x over previous
#include <cuda_runtime.h>
#include <cstdint>

#define N_NODES 100000
#define N_EDGES 1600000
#define N_PRED  500000
#define D       64
#define NB_SCAN 391   // ceil(N_NODES/256)

// ---------------- device scratch (alloc-free rule: static globals) ----------
__device__ int   g_deg_out[N_NODES];
__device__ int   g_deg_in [N_NODES];
__device__ float g_norm_out[N_NODES];
__device__ float g_norm_in [N_NODES];
__device__ int   g_rowstart[N_NODES];
__device__ int   g_cursor  [N_NODES];
__device__ int   g_blocksum[NB_SCAN];
__device__ int   g_blockoff[NB_SCAN];
__device__ int   g_csr_src [N_EDGES];
__device__ __align__(16) float g_xn [(size_t)N_NODES * D]; // layer-2 input (pre-scaled)
__device__ __align__(16) float g_agg[(size_t)N_NODES * D]; // aggregated (incl. norm_in)
__device__ __align__(16) float g_h  [(size_t)N_NODES * D]; // layer-2 output
__device__ __align__(16) float g_p  [(size_t)N_NODES * 16];// [pA | pB] per node

// ---------------- degree / norms --------------------------------------------

__global__ void k_zero_deg() {
    int i = blockIdx.x * blockDim.x + threadIdx.x;
    if (i < N_NODES) { g_deg_out[i] = 0; g_deg_in[i] = 0; }
}

__global__ void k_degree(const int* __restrict__ src, const int* __restrict__ dst) {
    int e = blockIdx.x * blockDim.x + threadIdx.x;
    if (e < N_EDGES) {
        atomicAdd(&g_deg_out[__ldg(&src[e])], 1);
        atomicAdd(&g_deg_in [__ldg(&dst[e])], 1);
    }
}

__global__ void k_norms() {
    int i = blockIdx.x * blockDim.x + threadIdx.x;
    if (i < N_NODES) {
        int dou = g_deg_out[i];
        int din = g_deg_in[i];
        g_norm_out[i] = dou > 0 ? rsqrtf((float)dou) : 0.f;
        g_norm_in [i] = din > 0 ? rsqrtf((float)din) : 0.f;
    }
}

// ---------------- exclusive scan of deg_in -> rowstart ----------------------

__global__ void k_scan1() {
    __shared__ int sh[256];
    int i = blockIdx.x * 256 + threadIdx.x;
    int v = (i < N_NODES) ? g_deg_in[i] : 0;
    sh[threadIdx.x] = v;
    __syncthreads();
#pragma unroll
    for (int off = 1; off < 256; off <<= 1) {
        int t = (threadIdx.x >= off) ? sh[threadIdx.x - off] : 0;
        __syncthreads();
        sh[threadIdx.x] += t;
        __syncthreads();
    }
    if (i < N_NODES) g_rowstart[i] = sh[threadIdx.x] - v;   // exclusive
    if (threadIdx.x == 255) g_blocksum[blockIdx.x] = sh[255];
}

__global__ void k_scan2() {   // single block of 512, scans NB_SCAN block sums
    __shared__ int sh[512];
    int v = (threadIdx.x < NB_SCAN) ? g_blocksum[threadIdx.x] : 0;
    sh[threadIdx.x] = v;
    __syncthreads();
#pragma unroll
    for (int off = 1; off < 512; off <<= 1) {
        int t = (threadIdx.x >= off) ? sh[threadIdx.x - off] : 0;
        __syncthreads();
        sh[threadIdx.x] += t;
        __syncthreads();
    }
    if (threadIdx.x < NB_SCAN) g_blockoff[threadIdx.x] = sh[threadIdx.x] - v;  // exclusive
}

__global__ void k_scan3() {
    int i = blockIdx.x * blockDim.x + threadIdx.x;
    if (i < N_NODES) {
        int rs = g_rowstart[i] + g_blockoff[i >> 8];
        g_rowstart[i] = rs;
        g_cursor[i] = rs;
    }
}

// ---------------- CSR bucket fill -------------------------------------------

__global__ void k_bucket(const int* __restrict__ src, const int* __restrict__ dst) {
    int e = blockIdx.x * blockDim.x + threadIdx.x;
    if (e < N_EDGES) {
        int d = __ldg(&dst[e]);
        int pos = atomicAdd(&g_cursor[d], 1);
        g_csr_src[pos] = __ldg(&src[e]);
    }
}

// ---------------- pull-mode aggregation -------------------------------------
// One warp per dst node. Lanes hold float2 accumulators (64 floats / warp).
// SRC_X=1: read raw x (kernel arg), scale each row by norm_out[src] inline.
// SRC_X=0: read g_xn device global directly (already pre-scaled).
// Epilogue applies norm_in so g_agg is GEMM-ready.
template <int SRC_X>
__global__ void __launch_bounds__(256)
k_aggregate(const float* __restrict__ xin) {
    int warp = (blockIdx.x * blockDim.x + threadIdx.x) >> 5;
    int lane = threadIdx.x & 31;
    if (warp >= N_NODES) return;

    const float* in = SRC_X ? xin : (const float*)g_xn;

    int start = g_rowstart[warp];
    int deg   = g_deg_in[warp];
    float2 acc = make_float2(0.f, 0.f);

    for (int base = 0; base < deg; base += 32) {
        int my = base + lane;
        int s_my = (my < deg) ? __ldg(&g_csr_src[start + my]) : 0;
        int cnt = min(32, deg - base);
#pragma unroll 4
        for (int k = 0; k < cnt; k++) {
            int s = __shfl_sync(0xffffffffu, s_my, k);
            float2 v = ((const float2*)(in + (size_t)s * D))[lane];
            if (SRC_X) {
                float no = __ldg(&g_norm_out[s]);
                v.x *= no; v.y *= no;
            }
            acc.x += v.x; acc.y += v.y;
        }
    }
    float ni = g_norm_in[warp];
    acc.x *= ni; acc.y *= ni;
    ((float2*)(g_agg + (size_t)warp * D))[lane] = acc;
}

// ---------------- node GEMM update ------------------------------------------
// out = f(g_agg @ W + b)   (g_agg already includes norm_in scaling)
// MODE 0: relu, then *norm_out -> g_xn.  MODE 1: plain -> g_h.
template <int MODE>
__global__ void __launch_bounds__(256, 2)
k_node_update(const float* __restrict__ W, const float* __restrict__ b) {
    const int t = threadIdx.x;
    const int c = t & 63;
    const int r = t >> 6;

    float w[D];
#pragma unroll
    for (int kk = 0; kk < D; kk++) w[kk] = __ldg(&W[kk * D + c]);
    const float bc = __ldg(&b[c]);

    __shared__ __align__(16) float vs[4][D];

    for (int base = blockIdx.x * 4; base < N_NODES; base += gridDim.x * 4) {
        int node = base + r;
        bool ok = (node < N_NODES);
        size_t off = (size_t)(ok ? node : 0) * D + c;
        if (ok) vs[r][c] = g_agg[off];
        __syncthreads();

        float acc = bc;
        const float4* vrow = (const float4*)vs[r];
#pragma unroll
        for (int q = 0; q < D / 4; q++) {
            float4 vv = vrow[q];
            acc = fmaf(vv.x, w[4 * q + 0], acc);
            acc = fmaf(vv.y, w[4 * q + 1], acc);
            acc = fmaf(vv.z, w[4 * q + 2], acc);
            acc = fmaf(vv.w, w[4 * q + 3], acc);
        }
        if (ok) {
            if (MODE == 0) {
                acc = fmaxf(acc, 0.f) * g_norm_out[node];
                g_xn[off] = acc;
            } else {
                g_h[off] = acc;
            }
        }
        __syncthreads();
    }
}

// ---------------- predictor --------------------------------------------------
// Per-node projection: g_p[n][0:8] = h[n] @ Wp[0:64], g_p[n][8:16] = h[n] @ Wp[64:128]
__global__ void __launch_bounds__(256, 2)
k_project(const float* __restrict__ Wp) {
    const int t = threadIdx.x;
    const int c  = t & 15;
    const int nl = t >> 4;

    const int rowoff = (c < 8) ? 0 : 64;
    const int cc = c & 7;
    float w[D];
#pragma unroll
    for (int kk = 0; kk < D; kk++) w[kk] = __ldg(&Wp[(rowoff + kk) * 8 + cc]);

    __shared__ __align__(16) float hs[16 * D];

    for (int base = blockIdx.x * 16; base < N_NODES; base += gridDim.x * 16) {
        if (base + (t >> 4) < N_NODES)
            ((float4*)hs)[t] = ((const float4*)(g_h + (size_t)base * D))[t];
        __syncthreads();

        int node = base + nl;
        if (node < N_NODES) {
            float acc = 0.f;
            const float4* vrow = (const float4*)(hs + nl * D);
#pragma unroll
            for (int q = 0; q < D / 4; q++) {
                float4 vv = vrow[q];
                acc = fmaf(vv.x, w[4 * q + 0], acc);
                acc = fmaf(vv.y, w[4 * q + 1], acc);
                acc = fmaf(vv.z, w[4 * q + 2], acc);
                acc = fmaf(vv.w, w[4 * q + 3], acc);
            }
            g_p[(size_t)node * 16 + c] = acc;
        }
        __syncthreads();
    }
}

__global__ void k_edge_pred(const int* __restrict__ psrc, const int* __restrict__ pdst,
                            const float* __restrict__ bp, float* __restrict__ out) {
    int e = blockIdx.x * blockDim.x + threadIdx.x;
    if (e >= N_PRED) return;
    int u = __ldg(&psrc[e]);
    int v = __ldg(&pdst[e]);
    const float4* pa = (const float4*)(g_p + (size_t)u * 16);
    const float4* pb = (const float4*)(g_p + (size_t)v * 16 + 8);
    float4 a0 = pa[0], a1 = pa[1];
    float4 c0 = pb[0], c1 = pb[1];
    float4 bp0 = ((const float4*)bp)[0];
    float4 bp1 = ((const float4*)bp)[1];
    float4 o0 = make_float4(a0.x + c0.x + bp0.x, a0.y + c0.y + bp0.y,
                            a0.z + c0.z + bp0.z, a0.w + c0.w + bp0.w);
    float4 o1 = make_float4(a1.x + c1.x + bp1.x, a1.y + c1.y + bp1.y,
                            a1.z + c1.z + bp1.z, a1.w + c1.w + bp1.w);
    ((float4*)out)[(size_t)e * 2 + 0] = o0;
    ((float4*)out)[(size_t)e * 2 + 1] = o1;
}

// ---------------- launch ----------------------------------------------------

extern "C" void kernel_launch(void* const* d_in, const int* in_sizes, int n_in,
                              void* d_out, int out_size) {
    const float* x    = (const float*)d_in[0];
    const int*   src  = (const int*)  d_in[1];
    const int*   dst  = (const int*)  d_in[2];
    const int*   psrc = (const int*)  d_in[3];
    const int*   pdst = (const int*)  d_in[4];
    const float* W1   = (const float*)d_in[5];
    const float* b1   = (const float*)d_in[6];
    const float* W2   = (const float*)d_in[7];
    const float* b2   = (const float*)d_in[8];
    const float* Wp   = (const float*)d_in[9];
    const float* bp   = (const float*)d_in[10];
    float* out = (float*)d_out;

    const int TB = 256;
    // degrees + norms
    k_zero_deg<<<(N_NODES + TB - 1) / TB, TB>>>();
    k_degree  <<<(N_EDGES + TB - 1) / TB, TB>>>(src, dst);
    k_norms   <<<(N_NODES + TB - 1) / TB, TB>>>();

    // CSR build (by dst)
    k_scan1<<<NB_SCAN, 256>>>();
    k_scan2<<<1, 512>>>();
    k_scan3<<<(N_NODES + TB - 1) / TB, TB>>>();
    k_bucket<<<(N_EDGES + TB - 1) / TB, TB>>>(src, dst);

    const int AGG_BLOCKS = N_NODES * 32 / TB;  // one warp per node, exact

    // layer 1: aggregate raw x with inline norm_out scaling, then GEMM+relu
    k_aggregate<1><<<AGG_BLOCKS, TB>>>(x);
    k_node_update<0><<<1024, TB>>>(W1, b1);    // -> g_xn (relu * norm_out)

    // layer 2: aggregate g_xn (referenced directly in device code)
    k_aggregate<0><<<AGG_BLOCKS, TB>>>(nullptr);
    k_node_update<1><<<1024, TB>>>(W2, b2);    // -> g_h

    // predictor
    k_project<<<(N_NODES + 15) / 16, TB>>>(Wp);
    k_edge_pred<<<(N_PRED + TB - 1) / TB, TB>>>(psrc, pdst, bp, out);
}

// round 5
// speedup vs baseline: 1.4210x; 1.0028x over previous
#include <cuda_runtime.h>
#include <cstdint>

#define N_NODES 100000
#define N_EDGES 1600000
#define N_PRED  500000
#define D       64
#define NB_SCAN 391   // ceil(N_NODES/256)

// ---------------- device scratch (alloc-free rule: static globals) ----------
__device__ int   g_deg_out[N_NODES];
__device__ int   g_deg_in [N_NODES];
__device__ float g_norm_out[N_NODES];
__device__ float g_norm_in [N_NODES];
__device__ int   g_rowstart[N_NODES];
__device__ int   g_cursor  [N_NODES];
__device__ int   g_blocksum[NB_SCAN];
__device__ int   g_blockoff[NB_SCAN];
__device__ int   g_csr_src [N_EDGES];
__device__ __align__(16) float g_xn [(size_t)N_NODES * D]; // layer-2 input (pre-scaled)
__device__ __align__(16) float g_agg[(size_t)N_NODES * D]; // aggregated (incl. norm_in)
__device__ __align__(16) float g_h  [(size_t)N_NODES * D]; // layer-2 output
__device__ __align__(16) float g_p  [(size_t)N_NODES * 16];// [pA | pB] per node

// ---------------- degree --------------------------------------------------

__global__ void k_zero_deg() {
    int i = blockIdx.x * blockDim.x + threadIdx.x;
    if (i < N_NODES) { g_deg_out[i] = 0; g_deg_in[i] = 0; }
}

__global__ void k_degree(const int* __restrict__ src, const int* __restrict__ dst) {
    int e = blockIdx.x * blockDim.x + threadIdx.x;
    if (e < N_EDGES) {
        atomicAdd(&g_deg_out[__ldg(&src[e])], 1);
        atomicAdd(&g_deg_in [__ldg(&dst[e])], 1);
    }
}

// ---------------- exclusive scan of deg_in -> rowstart ----------------------

__global__ void k_scan1() {
    __shared__ int sh[256];
    int i = blockIdx.x * 256 + threadIdx.x;
    int v = (i < N_NODES) ? g_deg_in[i] : 0;
    sh[threadIdx.x] = v;
    __syncthreads();
#pragma unroll
    for (int off = 1; off < 256; off <<= 1) {
        int t = (threadIdx.x >= off) ? sh[threadIdx.x - off] : 0;
        __syncthreads();
        sh[threadIdx.x] += t;
        __syncthreads();
    }
    if (i < N_NODES) g_rowstart[i] = sh[threadIdx.x] - v;   // exclusive
    if (threadIdx.x == 255) g_blocksum[blockIdx.x] = sh[255];
}

__global__ void k_scan2() {   // single block of 512, scans NB_SCAN block sums
    __shared__ int sh[512];
    int v = (threadIdx.x < NB_SCAN) ? g_blocksum[threadIdx.x] : 0;
    sh[threadIdx.x] = v;
    __syncthreads();
#pragma unroll
    for (int off = 1; off < 512; off <<= 1) {
        int t = (threadIdx.x >= off) ? sh[threadIdx.x - off] : 0;
        __syncthreads();
        sh[threadIdx.x] += t;
        __syncthreads();
    }
    if (threadIdx.x < NB_SCAN) g_blockoff[threadIdx.x] = sh[threadIdx.x] - v;  // exclusive
}

// finalize rowstart/cursor AND compute norms (fused; both are over N_NODES)
__global__ void k_scan3_norms() {
    int i = blockIdx.x * blockDim.x + threadIdx.x;
    if (i < N_NODES) {
        int rs = g_rowstart[i] + g_blockoff[i >> 8];
        g_rowstart[i] = rs;
        g_cursor[i] = rs;
        int dou = g_deg_out[i];
        int din = g_deg_in[i];
        g_norm_out[i] = dou > 0 ? rsqrtf((float)dou) : 0.f;
        g_norm_in [i] = din > 0 ? rsqrtf((float)din) : 0.f;
    }
}

// ---------------- CSR bucket fill -------------------------------------------

__global__ void k_bucket(const int* __restrict__ src, const int* __restrict__ dst) {
    int e = blockIdx.x * blockDim.x + threadIdx.x;
    if (e < N_EDGES) {
        int d = __ldg(&dst[e]);
        int pos = atomicAdd(&g_cursor[d], 1);
        g_csr_src[pos] = __ldg(&src[e]);
    }
}

// ---------------- pull-mode aggregation -------------------------------------
// One warp per dst node; the two half-warps process neighbors k and k+1
// concurrently, each lane loading a float4 (16 lanes x 16B = 256B row).
// SRC_X=1: read raw x (kernel arg), scale rows by norm_out[src] inline.
// SRC_X=0: read g_xn device global directly (already pre-scaled).
// Epilogue combines half-warps (shfl-xor 16) and applies norm_in.
template <int SRC_X>
__global__ void __launch_bounds__(256)
k_aggregate(const float* __restrict__ xin) {
    int warp = (blockIdx.x * blockDim.x + threadIdx.x) >> 5;
    int lane = threadIdx.x & 31;
    if (warp >= N_NODES) return;

    const float* in = SRC_X ? xin : (const float*)g_xn;
    const int half = lane >> 4;   // which neighbor of the pair
    const int col  = lane & 15;   // float4 column within the row

    int start = g_rowstart[warp];
    int deg   = g_deg_in[warp];
    float4 acc = make_float4(0.f, 0.f, 0.f, 0.f);

    for (int base = 0; base < deg; base += 32) {
        int my = base + lane;
        int s_my = (my < deg) ? __ldg(&g_csr_src[start + my]) : 0;
        int cnt = min(32, deg - base);
#pragma unroll 4
        for (int k2 = 0; k2 < cnt; k2 += 2) {
            int idx = k2 + half;
            int s = __shfl_sync(0xffffffffu, s_my, idx & 31);
            if (idx < cnt) {
                float4 v = ((const float4*)(in + (size_t)s * D))[col];
                if (SRC_X) {
                    float no = __ldg(&g_norm_out[s]);
                    v.x *= no; v.y *= no; v.z *= no; v.w *= no;
                }
                acc.x += v.x; acc.y += v.y; acc.z += v.z; acc.w += v.w;
            }
        }
    }
    // combine the two half-warps (same columns, disjoint neighbor subsets)
    acc.x += __shfl_xor_sync(0xffffffffu, acc.x, 16);
    acc.y += __shfl_xor_sync(0xffffffffu, acc.y, 16);
    acc.z += __shfl_xor_sync(0xffffffffu, acc.z, 16);
    acc.w += __shfl_xor_sync(0xffffffffu, acc.w, 16);

    if (half == 0) {
        float ni = g_norm_in[warp];
        acc.x *= ni; acc.y *= ni; acc.z *= ni; acc.w *= ni;
        ((float4*)(g_agg + (size_t)warp * D))[col] = acc;
    }
}

// ---------------- node GEMM update ------------------------------------------
// out = f(g_agg @ W + b)   (g_agg already includes norm_in scaling)
// MODE 0: relu, then *norm_out -> g_xn.  MODE 1: plain -> g_h.
template <int MODE>
__global__ void __launch_bounds__(256, 2)
k_node_update(const float* __restrict__ W, const float* __restrict__ b) {
    const int t = threadIdx.x;
    const int c = t & 63;
    const int r = t >> 6;

    float w[D];
#pragma unroll
    for (int kk = 0; kk < D; kk++) w[kk] = __ldg(&W[kk * D + c]);
    const float bc = __ldg(&b[c]);

    __shared__ __align__(16) float vs[4][D];

    for (int base = blockIdx.x * 4; base < N_NODES; base += gridDim.x * 4) {
        int node = base + r;
        bool ok = (node < N_NODES);
        size_t off = (size_t)(ok ? node : 0) * D + c;
        if (ok) vs[r][c] = g_agg[off];
        __syncthreads();

        float acc = bc;
        const float4* vrow = (const float4*)vs[r];
#pragma unroll
        for (int q = 0; q < D / 4; q++) {
            float4 vv = vrow[q];
            acc = fmaf(vv.x, w[4 * q + 0], acc);
            acc = fmaf(vv.y, w[4 * q + 1], acc);
            acc = fmaf(vv.z, w[4 * q + 2], acc);
            acc = fmaf(vv.w, w[4 * q + 3], acc);
        }
        if (ok) {
            if (MODE == 0) {
                acc = fmaxf(acc, 0.f) * g_norm_out[node];
                g_xn[off] = acc;
            } else {
                g_h[off] = acc;
            }
        }
        __syncthreads();
    }
}

// ---------------- predictor --------------------------------------------------
// Per-node projection: g_p[n][0:8] = h[n] @ Wp[0:64], g_p[n][8:16] = h[n] @ Wp[64:128]
__global__ void __launch_bounds__(256, 2)
k_project(const float* __restrict__ Wp) {
    const int t = threadIdx.x;
    const int c  = t & 15;
    const int nl = t >> 4;

    const int rowoff = (c < 8) ? 0 : 64;
    const int cc = c & 7;
    float w[D];
#pragma unroll
    for (int kk = 0; kk < D; kk++) w[kk] = __ldg(&Wp[(rowoff + kk) * 8 + cc]);

    __shared__ __align__(16) float hs[16 * D];

    for (int base = blockIdx.x * 16; base < N_NODES; base += gridDim.x * 16) {
        if (base + (t >> 4) < N_NODES)
            ((float4*)hs)[t] = ((const float4*)(g_h + (size_t)base * D))[t];
        __syncthreads();

        int node = base + nl;
        if (node < N_NODES) {
            float acc = 0.f;
            const float4* vrow = (const float4*)(hs + nl * D);
#pragma unroll
            for (int q = 0; q < D / 4; q++) {
                float4 vv = vrow[q];
                acc = fmaf(vv.x, w[4 * q + 0], acc);
                acc = fmaf(vv.y, w[4 * q + 1], acc);
                acc = fmaf(vv.z, w[4 * q + 2], acc);
                acc = fmaf(vv.w, w[4 * q + 3], acc);
            }
            g_p[(size_t)node * 16 + c] = acc;
        }
        __syncthreads();
    }
}

__global__ void k_edge_pred(const int* __restrict__ psrc, const int* __restrict__ pdst,
                            const float* __restrict__ bp, float* __restrict__ out) {
    int e = blockIdx.x * blockDim.x + threadIdx.x;
    if (e >= N_PRED) return;
    int u = __ldg(&psrc[e]);
    int v = __ldg(&pdst[e]);
    const float4* pa = (const float4*)(g_p + (size_t)u * 16);
    const float4* pb = (const float4*)(g_p + (size_t)v * 16 + 8);
    float4 a0 = pa[0], a1 = pa[1];
    float4 c0 = pb[0], c1 = pb[1];
    float4 bp0 = ((const float4*)bp)[0];
    float4 bp1 = ((const float4*)bp)[1];
    float4 o0 = make_float4(a0.x + c0.x + bp0.x, a0.y + c0.y + bp0.y,
                            a0.z + c0.z + bp0.z, a0.w + c0.w + bp0.w);
    float4 o1 = make_float4(a1.x + c1.x + bp1.x, a1.y + c1.y + bp1.y,
                            a1.z + c1.z + bp1.z, a1.w + c1.w + bp1.w);
    ((float4*)out)[(size_t)e * 2 + 0] = o0;
    ((float4*)out)[(size_t)e * 2 + 1] = o1;
}

// ---------------- launch ----------------------------------------------------

extern "C" void kernel_launch(void* const* d_in, const int* in_sizes, int n_in,
                              void* d_out, int out_size) {
    const float* x    = (const float*)d_in[0];
    const int*   src  = (const int*)  d_in[1];
    const int*   dst  = (const int*)  d_in[2];
    const int*   psrc = (const int*)  d_in[3];
    const int*   pdst = (const int*)  d_in[4];
    const float* W1   = (const float*)d_in[5];
    const float* b1   = (const float*)d_in[6];
    const float* W2   = (const float*)d_in[7];
    const float* b2   = (const float*)d_in[8];
    const float* Wp   = (const float*)d_in[9];
    const float* bp   = (const float*)d_in[10];
    float* out = (float*)d_out;

    const int TB = 256;
    // degrees
    k_zero_deg<<<(N_NODES + TB - 1) / TB, TB>>>();
    k_degree  <<<(N_EDGES + TB - 1) / TB, TB>>>(src, dst);

    // CSR build (by dst) + norms
    k_scan1<<<NB_SCAN, 256>>>();
    k_scan2<<<1, 512>>>();
    k_scan3_norms<<<(N_NODES + TB - 1) / TB, TB>>>();
    k_bucket<<<(N_EDGES + TB - 1) / TB, TB>>>(src, dst);

    const int AGG_BLOCKS = N_NODES * 32 / TB;  // one warp per node, exact

    // layer 1: aggregate raw x with inline norm_out scaling, then GEMM+relu
    k_aggregate<1><<<AGG_BLOCKS, TB>>>(x);
    k_node_update<0><<<1024, TB>>>(W1, b1);    // -> g_xn (relu * norm_out)

    // layer 2: aggregate g_xn (referenced directly in device code)
    k_aggregate<0><<<AGG_BLOCKS, TB>>>(nullptr);
    k_node_update<1><<<1024, TB>>>(W2, b2);    // -> g_h

    // predictor
    k_project<<<(N_NODES + 15) / 16, TB>>>(Wp);
    k_edge_pred<<<(N_PRED + TB - 1) / TB, TB>>>(psrc, pdst, bp, out);
}